// round 2
// baseline (speedup 1.0000x reference)
#include <cuda_runtime.h>
#include <cuda_bf16.h>

// Problem dims (fixed by the dataset's setup_inputs)
#define S_DIM 128
#define A_DIM 96
#define B_DIM 256
#define LX    512
#define LY    256

// Scratch: C'[s][a] = -softmax(P, axis=1)[s][a]   (so that cost-1 = C')
__device__ float g_Cn[S_DIM * A_DIM];

// One warp per row of P. A_DIM = 96 = 3 elems per lane.
__global__ void softmax_neg_kernel(const float* __restrict__ P) {
    int row  = blockIdx.x;
    int lane = threadIdx.x;
    const float* pr = P + row * A_DIM;
    float v0 = pr[lane], v1 = pr[lane + 32], v2 = pr[lane + 64];
    float m = fmaxf(v0, fmaxf(v1, v2));
    #pragma unroll
    for (int o = 16; o > 0; o >>= 1) m = fmaxf(m, __shfl_xor_sync(0xffffffffu, m, o));
    float e0 = expf(v0 - m), e1 = expf(v1 - m), e2 = expf(v2 - m);
    float s = e0 + e1 + e2;
    #pragma unroll
    for (int o = 16; o > 0; o >>= 1) s += __shfl_xor_sync(0xffffffffu, s, o);
    float inv = -1.0f / s;
    g_Cn[row * A_DIM + lane     ] = e0 * inv;
    g_Cn[row * A_DIM + lane + 32] = e1 * inv;
    g_Cn[row * A_DIM + lane + 64] = e2 * inv;
}

// One warp per batch. Lane owns columns j = 8*lane+1 .. 8*lane+8 (in D' = D - j space).
// Row update: G[j] = min(D'[j] + 1, D'[j-1] + c'[j]);  D'_new = prefix-min(G) seeded with r.
__global__ void __launch_bounds__(32, 16) dp_kernel(
    const int* __restrict__ xs,
    const int* __restrict__ ys,
    const int* __restrict__ xlen,
    const int* __restrict__ ylen,
    float* __restrict__ out)
{
    const int b    = blockIdx.x;
    const int lane = threadIdx.x;
    const int xl   = xlen[b] - 1;   // target row   (1..LX-1)
    const int yl   = ylen[b] - 1;   // target col   (1..LY-1)

    const int* xsb = xs + (size_t)b * LX;
    const int* ysb = ys + (size_t)b * LY;

    // ys indices for this lane's 8 columns (fixed across all rows)
    int y[8];
    #pragma unroll
    for (int k = 0; k < 8; ++k) y[k] = ysb[lane * 8 + k];

    // D' state (row 0: D'[j] = 0)
    float D[8];
    #pragma unroll
    for (int k = 0; k < 8; ++k) D[k] = 0.0f;

    const int t_target = (yl - 1) >> 3;
    const int k_target = (yl - 1) & 7;

    // --- software pipeline: costs for row r+1 fetched during row r ---
    int x0 = xsb[0];
    float c[8];
    #pragma unroll
    for (int k = 0; k < 8; ++k) c[k] = g_Cn[x0 * A_DIM + y[k]];
    int xnext = (xl > 1) ? xsb[1] : 0;

    for (int r = 1; ; ++r) {
        // prefetch costs for row r+1 (cost row index r uses xs[r])
        float cn[8];
        if (r < xl) {
            #pragma unroll
            for (int k = 0; k < 8; ++k) cn[k] = g_Cn[xnext * A_DIM + y[k]];
        }
        int xnn = (r + 1 < xl) ? xsb[r + 1] : 0;

        // left neighbor D'[j-1] for k=0 (column 0 is analytic: D'_{r-1}[0] = r-1)
        float Dl = __shfl_up_sync(0xffffffffu, D[7], 1);
        if (lane == 0) Dl = (float)(r - 1);

        // G + local inclusive prefix-min over this lane's 8 columns
        float M[8];
        M[0] = fminf(D[0] + 1.0f, Dl + c[0]);
        #pragma unroll
        for (int k = 1; k < 8; ++k) {
            float g = fminf(D[k] + 1.0f, D[k - 1] + c[k]);
            M[k] = fminf(M[k - 1], g);
        }

        // warp inclusive min-scan of per-lane totals
        float T = M[7];
        #pragma unroll
        for (int o = 1; o < 32; o <<= 1) {
            float u = __shfl_up_sync(0xffffffffu, T, o);
            if (lane >= o) T = fminf(T, u);
        }
        // exclusive prefix for this lane, seeded with column-0 value G[0] = r
        float X  = __shfl_up_sync(0xffffffffu, T, 1);
        float Pm = (lane == 0) ? (float)r : fminf((float)r, X);

        #pragma unroll
        for (int k = 0; k < 8; ++k) D[k] = fminf(Pm, M[k]);

        if (r == xl) {
            if (lane == t_target) out[b] = D[k_target] + (float)yl;  // back to D-space
            break;
        }
        #pragma unroll
        for (int k = 0; k < 8; ++k) c[k] = cn[k];
        xnext = xnn;
    }
}

extern "C" void kernel_launch(void* const* d_in, const int* in_sizes, int n_in,
                              void* d_out, int out_size) {
    const float* P    = (const float*)d_in[0];
    const int*   xs   = (const int*)d_in[1];
    const int*   ys   = (const int*)d_in[2];
    const int*   xlen = (const int*)d_in[3];
    const int*   ylen = (const int*)d_in[4];
    float*       out  = (float*)d_out;

    softmax_neg_kernel<<<S_DIM, 32>>>(P);
    dp_kernel<<<B_DIM, 32>>>(xs, ys, xlen, ylen, out);
}

// round 3
// speedup vs baseline: 1.5322x; 1.5322x over previous
#include <cuda_runtime.h>
#include <cuda_bf16.h>

// Problem dims (fixed by the dataset's setup_inputs)
#define S_DIM 128
#define A_DIM 96
#define B_DIM 256
#define LX    512
#define LY    256

// Scratch: C'[s][a] = -softmax(P, axis=1)[s][a]   (cost - 1 = C')
__device__ float g_Cn[S_DIM * A_DIM];

// One warp per row of P. A_DIM = 96 = 3 elems per lane.
__global__ void softmax_neg_kernel(const float* __restrict__ P) {
    int row  = blockIdx.x;
    int lane = threadIdx.x;
    const float* pr = P + row * A_DIM;
    float v0 = pr[lane], v1 = pr[lane + 32], v2 = pr[lane + 64];
    float m = fmaxf(v0, fmaxf(v1, v2));
    #pragma unroll
    for (int o = 16; o > 0; o >>= 1) m = fmaxf(m, __shfl_xor_sync(0xffffffffu, m, o));
    float e0 = expf(v0 - m), e1 = expf(v1 - m), e2 = expf(v2 - m);
    float s = e0 + e1 + e2;
    #pragma unroll
    for (int o = 16; o > 0; o >>= 1) s += __shfl_xor_sync(0xffffffffu, s, o);
    float inv = -1.0f / s;
    g_Cn[row * A_DIM + lane     ] = e0 * inv;
    g_Cn[row * A_DIM + lane + 32] = e1 * inv;
    g_Cn[row * A_DIM + lane + 64] = e2 * inv;
}

// One warp per batch, lane-skewed wavefront.
// Lane L owns columns j = 8L+1 .. 8L+8 (D' = D - j space) and at step s
// processes DP row r = s - L. Recurrence per cell:
//   E'[j]    = min(D'_{r-1}[j] + 1, D'_{r-1}[j-1] + c')      (c' = -softmax)
//   D'_r[j]  = min(E'[j], D'_r[j-1])                          (running min)
// Cross-lane: D'_r[jb-1] comes from lane L-1's D[7] produced one step earlier
// (single shfl per step). Col 0 boundary is analytic: D'_r[0] = r.
__global__ void __launch_bounds__(32, 16) dp_kernel(
    const int* __restrict__ xs,
    const int* __restrict__ ys,
    const int* __restrict__ xlen,
    const int* __restrict__ ylen,
    float* __restrict__ out)
{
    const int b    = blockIdx.x;
    const int lane = threadIdx.x;
    const int xl   = xlen[b] - 1;   // target row (1..LX-1)
    const int yl   = ylen[b] - 1;   // target col (1..LY-1)

    const int* xsb = xs + (size_t)b * LX;
    const int* ysb = ys + (size_t)b * LY;

    int y[8];
    #pragma unroll
    for (int k = 0; k < 8; ++k) y[k] = ysb[lane * 8 + k];

    float D[8];
    #pragma unroll
    for (int k = 0; k < 8; ++k) D[k] = 0.0f;   // row 0: D'[j] = 0

    const int t_lane = (yl - 1) >> 3;
    const int k_t    = (yl - 1) & 7;
    const int s_end  = xl + t_lane;   // lane t_lane hits row xl at this step

    float Dl    = 0.0f;              // D'_r[jb-1] for the upcoming step
    float bprev = 0.0f;              // D'_{r-1}[jb-1]
    float rf    = (float)(1 - lane); // float(r) at current step (incremented)

    // --- cost pipeline: c[] = costs for the row processed THIS step ---
    float c[8];
    int xv;                          // xs value feeding NEXT step's cost load
    {
        int r1  = 1 - lane;                       // row at step 1
        int rc1 = min(max(r1 - 1, 0), xl - 1);
        int x0  = xsb[rc1];
        #pragma unroll
        for (int k = 0; k < 8; ++k) c[k] = g_Cn[x0 * A_DIM + y[k]];
        int rc2 = min(max(r1, 0), xl - 1);        // xs[r1] feeds row r1+1
        xv = xsb[rc2];
    }

    const bool is0 = (lane == 0);

    #pragma unroll 2
    for (int s = 1; s <= s_end; ++s) {
        const int r = s - lane;

        // prefetch costs for row r+1 (uses xs[r]) and xs for row r+2
        float cn[8];
        #pragma unroll
        for (int k = 0; k < 8; ++k) cn[k] = g_Cn[xv * A_DIM + y[k]];
        int rc  = min(max(r + 1, 0), xl - 1);
        int xv2 = xsb[rc];

        float Dl_eff = is0 ? rf : Dl;   // lane 0 boundary: D'_r[0] = r

        float nD[8];
        {
            float e0 = fminf(D[0] + 1.0f, bprev + c[0]);
            nD[0] = fminf(e0, Dl_eff);
        }
        #pragma unroll
        for (int k = 1; k < 8; ++k) {
            float e = fminf(D[k] + 1.0f, D[k - 1] + c[k]);
            nD[k] = fminf(e, nD[k - 1]);
        }

        const bool active = (r >= 1) & (r <= xl);
        #pragma unroll
        for (int k = 0; k < 8; ++k) D[k] = active ? nD[k] : D[k];

        float sh = __shfl_up_sync(0xffffffffu, D[7], 1);
        bprev = Dl_eff;   // next step's D'_{r}[jb-1] (prev-row boundary)
        Dl    = sh;
        #pragma unroll
        for (int k = 0; k < 8; ++k) c[k] = cn[k];
        xv  = xv2;
        rf += 1.0f;
    }

    // lane t_lane froze its D at row xl; convert back to D-space
    if (lane == t_lane) out[b] = D[k_t] + (float)yl;
}

extern "C" void kernel_launch(void* const* d_in, const int* in_sizes, int n_in,
                              void* d_out, int out_size) {
    const float* P    = (const float*)d_in[0];
    const int*   xs   = (const int*)d_in[1];
    const int*   ys   = (const int*)d_in[2];
    const int*   xlen = (const int*)d_in[3];
    const int*   ylen = (const int*)d_in[4];
    float*       out  = (float*)d_out;

    softmax_neg_kernel<<<S_DIM, 32>>>(P);
    dp_kernel<<<B_DIM, 32>>>(xs, ys, xlen, ylen, out);
}

// round 4
// speedup vs baseline: 1.9901x; 1.2989x over previous
#include <cuda_runtime.h>
#include <cuda_bf16.h>

// Problem dims (fixed by the dataset's setup_inputs)
#define S_DIM 128
#define A_DIM 96
#define B_DIM 256
#define LX    512
#define LY    256

// Scratch: C'[s][a] = -softmax(P, axis=1)[s][a]   (cost - 1 = C')
__device__ float g_Cn[S_DIM * A_DIM];

// One warp per row of P. A_DIM = 96 = 3 elems per lane.
__global__ void softmax_neg_kernel(const float* __restrict__ P) {
    int row  = blockIdx.x;
    int lane = threadIdx.x;
    const float* pr = P + row * A_DIM;
    float v0 = pr[lane], v1 = pr[lane + 32], v2 = pr[lane + 64];
    float m = fmaxf(v0, fmaxf(v1, v2));
    #pragma unroll
    for (int o = 16; o > 0; o >>= 1) m = fmaxf(m, __shfl_xor_sync(0xffffffffu, m, o));
    float e0 = expf(v0 - m), e1 = expf(v1 - m), e2 = expf(v2 - m);
    float s = e0 + e1 + e2;
    #pragma unroll
    for (int o = 16; o > 0; o >>= 1) s += __shfl_xor_sync(0xffffffffu, s, o);
    float inv = -1.0f / s;
    g_Cn[row * A_DIM + lane     ] = e0 * inv;
    g_Cn[row * A_DIM + lane + 32] = e1 * inv;
    g_Cn[row * A_DIM + lane + 64] = e2 * inv;
}

// One warp per batch, lane-skewed wavefront, log-depth in-lane prefix-min,
// depth-4 cost prefetch pipeline. Lane L owns columns j = 8L+1..8L+8
// (D' = D - j space) and at step s processes DP row r = s - L.
//   E'[j]   = min(D'_{r-1}[j] + 1, D'_{r-1}[j-1] + c')
//   D'_r[j] = min(prefixmin(E')[j], boundary)   boundary = D'_r[8L] (shfl) or r (lane 0)
__global__ void __launch_bounds__(32, 4) dp_kernel(
    const int* __restrict__ xs,
    const int* __restrict__ ys,
    const int* __restrict__ xlen,
    const int* __restrict__ ylen,
    float* __restrict__ out)
{
    const int b    = blockIdx.x;
    const int lane = threadIdx.x;
    const int xl   = xlen[b] - 1;   // target row (1..LX-1)
    const int yl   = ylen[b] - 1;   // target col (1..LY-1)

    const int* xsb = xs + (size_t)b * LX;
    const int* ysb = ys + (size_t)b * LY;

    int y[8];
    #pragma unroll
    for (int k = 0; k < 8; ++k) y[k] = ysb[lane * 8 + k];

    float D[8];
    #pragma unroll
    for (int k = 0; k < 8; ++k) D[k] = 0.0f;   // row 0: D'[j] = 0

    const int t_lane = (yl - 1) >> 3;
    const int k_t    = (yl - 1) & 7;
    const int s_end  = xl + t_lane;     // lane t_lane reaches row xl here
    const int xcap   = xl - 1;          // clamp bound for xs index

    float Dl    = 0.0f;                 // shfl'd boundary for upcoming step
    float bprev = 0.0f;                 // D'_{r-1}[jb-1]
    float rf    = (float)(1 - lane);    // float(r) for lane-0 boundary
    const bool is0 = (lane == 0);

    const int r1 = 1 - lane;            // row at step 1

    // cost pipeline: cb[p] = gathered costs for row (r + p); row q uses xs[q-1]
    float cb[4][8];
    #pragma unroll
    for (int p = 0; p < 4; ++p) {
        int q  = r1 + p - 1;
        int xv = xsb[min(max(q, 0), xcap)];
        #pragma unroll
        for (int k = 0; k < 8; ++k) cb[p][k] = g_Cn[xv * A_DIM + y[k]];
    }
    // xs pipeline (depth 3): xsv[i] = xs[clamp(r1 + 3 + i)] feeds cost row r1+4+i
    int xsv[3];
    #pragma unroll
    for (int i = 0; i < 3; ++i) xsv[i] = xsb[min(max(r1 + 3 + i, 0), xcap)];

    #pragma unroll 4
    for (int s = 1; s <= s_end; ++s) {
        const int r = s - lane;

        // prefetch: cost for row r+4 (uses xs[r+3] = xsv[0]); refill xs pipe
        float cnew[8];
        #pragma unroll
        for (int k = 0; k < 8; ++k) cnew[k] = g_Cn[xsv[0] * A_DIM + y[k]];
        int xnew = xsb[min(max(r + 6, 0), xcap)];

        float Dl_eff = is0 ? rf : Dl;   // boundary D'_r[8L] (lane0: analytic r)

        // E and its in-lane inclusive prefix-min (log depth)
        float E[8];
        E[0] = fminf(D[0] + 1.0f, bprev + cb[0][0]);
        #pragma unroll
        for (int k = 1; k < 8; ++k)
            E[k] = fminf(D[k] + 1.0f, D[k - 1] + cb[0][k]);

        float t1[8];
        t1[0] = E[0];
        #pragma unroll
        for (int k = 1; k < 8; ++k) t1[k] = fminf(E[k], E[k - 1]);
        float t2[8];
        t2[0] = t1[0]; t2[1] = t1[1];
        #pragma unroll
        for (int k = 2; k < 8; ++k) t2[k] = fminf(t1[k], t1[k - 2]);
        float t3[8];
        #pragma unroll
        for (int k = 0; k < 4; ++k) t3[k] = t2[k];
        #pragma unroll
        for (int k = 4; k < 8; ++k) t3[k] = fminf(t2[k], t2[k - 4]);

        // freeze only during ramp-in (r < 1); ramp-out garbage is never consumed
        const bool act = (s > lane);
        #pragma unroll
        for (int k = 0; k < 8; ++k)
            D[k] = act ? fminf(t3[k], Dl_eff) : D[k];

        float sh = __shfl_up_sync(0xffffffffu, D[7], 1);
        bprev = Dl_eff;
        Dl    = sh;
        rf   += 1.0f;

        // rotate pipelines (register renames under unroll)
        #pragma unroll
        for (int k = 0; k < 8; ++k) {
            cb[0][k] = cb[1][k]; cb[1][k] = cb[2][k];
            cb[2][k] = cb[3][k]; cb[3][k] = cnew[k];
        }
        xsv[0] = xsv[1]; xsv[1] = xsv[2]; xsv[2] = xnew;
    }

    // lane t_lane's D holds row xl; convert back to D-space
    if (lane == t_lane) out[b] = D[k_t] + (float)yl;
}

extern "C" void kernel_launch(void* const* d_in, const int* in_sizes, int n_in,
                              void* d_out, int out_size) {
    const float* P    = (const float*)d_in[0];
    const int*   xs   = (const int*)d_in[1];
    const int*   ys   = (const int*)d_in[2];
    const int*   xlen = (const int*)d_in[3];
    const int*   ylen = (const int*)d_in[4];
    float*       out  = (float*)d_out;

    softmax_neg_kernel<<<S_DIM, 32>>>(P);
    dp_kernel<<<B_DIM, 32>>>(xs, ys, xlen, ylen, out);
}